// round 7
// baseline (speedup 1.0000x reference)
#include <cuda_runtime.h>
#include <cuda_bf16.h>

#define NB    8
#define NV    2048
#define NF    512
#define VOX   96
#define NSLAB 16
#define SLABW 6
#define DELTA 0.03125f

#define STEPF (2.0f / 96.0f)
#define PZ0F  (-95.0f / 96.0f)

// Exact-test record (bit-identical to R2 form), 4 float4 per facet:
//  e0 = B00 B01 B02 |det|   e1 = B10 B11 B12 v3x
//  e2 = B20 B21 B22 v3y     e3 = v3z pad pad pad
__device__ float4 g_ex[NB * NF * 4];

// Interval record, 4 float4 per facet, lo/hi preordered:
//  q_r = (Ex, Ey, Ec, w):  lo_r = Ex*px + Ey*py + Ec ;  hi_r = lo_r + w (w>=0)
__device__ float4 g_int[NB * NF * 4];

__device__ int4 g_bb[NB * NF];            // voxel bbox (ixLo,ixHi,iyLo,iyHi)
__device__ int  g_cnt [NB * NSLAB];       // per-(batch,slab) facet list counts
__device__ int  g_list[NB * NSLAB * NF];  // facet lists (global facet ids)

__global__ void zero_cnt_kernel() { g_cnt[threadIdx.x] = 0; }

// ---------------------------------------------------------------------------
// Prep: one thread per facet. Records + bbox + slab-list append.
// ---------------------------------------------------------------------------
__global__ void prep_kernel(
    const float* __restrict__ vertices,   // [NB, NV, 3] f32
    const int*   __restrict__ facets)     // [NB, NF, 4] i32
{
    const int id = blockIdx.x * 256 + threadIdx.x;   // < NB*NF
    const int b = id >> 9;

    const float* Vb = vertices + (size_t)b * NV * 3;
    const int* Fp = facets + (size_t)id * 4;
    const int i0 = Fp[0] & (NV - 1);
    const int i1 = Fp[1] & (NV - 1);
    const int i2 = Fp[2] & (NV - 1);
    const int i3 = Fp[3] & (NV - 1);

    const float v0x = Vb[i0*3+0], v0y = Vb[i0*3+1], v0z = Vb[i0*3+2];
    const float v1x = Vb[i1*3+0], v1y = Vb[i1*3+1], v1z = Vb[i1*3+2];
    const float v2x = Vb[i2*3+0], v2y = Vb[i2*3+1], v2z = Vb[i2*3+2];
    const float v3x = Vb[i3*3+0], v3y = Vb[i3*3+1], v3z = Vb[i3*3+2];

    const float a  = v0x - v3x, bb = v1x - v3x, c  = v2x - v3x;
    const float d  = v0y - v3y, e  = v1y - v3y, ff = v2y - v3y;
    const float g  = v0z - v3z, h  = v1z - v3z, ii = v2z - v3z;

    const float A00 = e*ii - ff*h, A01 = c*h  - bb*ii, A02 = bb*ff - c*e;
    const float A10 = ff*g - d*ii, A11 = a*ii - c*g,   A12 = c*d  - a*ff;
    const float A20 = d*h  - e*g,  A21 = bb*g - a*h,   A22 = a*e  - bb*d;

    const float det = a*A00 + bb*A10 + c*A20;
    const float sd  = (det < 0.0f) ? -1.0f : 1.0f;
    float D = det * sd;
    if (det == 0.0f) D = -1.0f;

    const float B[3][3] = { {A00*sd, A01*sd, A02*sd},
                            {A10*sd, A11*sd, A12*sd},
                            {A20*sd, A21*sd, A22*sd} };

    g_ex[id*4+0] = make_float4(B[0][0], B[0][1], B[0][2], D);
    g_ex[id*4+1] = make_float4(B[1][0], B[1][1], B[1][2], v3x);
    g_ex[id*4+2] = make_float4(B[2][0], B[2][1], B[2][2], v3y);
    g_ex[id*4+3] = make_float4(v3z, 0.0f, 0.0f, 0.0f);

    float R0[4], R1[4], Kc[4], Bz[4];
    #pragma unroll
    for (int r = 0; r < 3; r++) {
        R0[r] = B[r][0]; R1[r] = B[r][1];
        float bz = B[r][2];
        if (fabsf(bz) < 1e-30f) bz = 1e-30f;
        Bz[r] = bz;
        Kc[r] = bz * (PZ0F - v3z) - B[r][0]*v3x - B[r][1]*v3y;
    }
    R0[3] = R0[0] + R0[1] + R0[2];
    R1[3] = R1[0] + R1[1] + R1[2];
    {
        float bz = Bz[0] + Bz[1] + Bz[2];
        if (fabsf(bz) < 1e-30f) bz = 1e-30f;
        Bz[3] = bz;
        Kc[3] = Kc[0] + Kc[1] + Kc[2];
    }

    #pragma unroll
    for (int r = 0; r < 4; r++) {
        const float G   = Bz[r] * STEPF;
        const float nG  = -1.0f / G;
        const float DoG = D / G;
        const float Ex  = R0[r] * nG;
        const float Ey  = R1[r] * nG;
        const float Ec  = Kc[r] * nG + fminf(DoG, 0.0f);
        const float w   = fabsf(DoG);
        g_int[id*4+r] = make_float4(Ex, Ey, Ec, w);
    }

    // voxel bbox with safety pad
    const float pad = 1e-5f;
    const float xmn = fminf(fminf(v0x, v1x), fminf(v2x, v3x)) - pad;
    const float xmx = fmaxf(fmaxf(v0x, v1x), fmaxf(v2x, v3x)) + pad;
    const float ymn = fminf(fminf(v0y, v1y), fminf(v2y, v3y)) - pad;
    const float ymx = fmaxf(fmaxf(v0y, v1y), fmaxf(v2y, v3y)) + pad;

    int4 bbv;
    bbv.x = max(0,  (int)ceilf (48.0f * xmn + 47.5f));
    bbv.y = min(95, (int)floorf(48.0f * xmx + 47.5f));
    bbv.z = max(0,  (int)ceilf (48.0f * ymn + 47.5f));
    bbv.w = min(95, (int)floorf(48.0f * ymx + 47.5f));
    if (D < 0.0f) { bbv.x = 1; bbv.y = 0; }   // degenerate: empty
    g_bb[id] = bbv;

    if (bbv.x <= bbv.y) {
        const int sLo = bbv.x / SLABW;
        const int sHi = bbv.y / SLABW;
        for (int s = sLo; s <= sHi; s++) {
            const int slot = b * NSLAB + s;
            const int pos = atomicAdd(&g_cnt[slot], 1);
            g_list[slot * NF + pos] = id;
        }
    }
}

// ---------------------------------------------------------------------------
// Fused scatter+expand: block = (batch, 6-plane x-slab). Warp w owns plane
// ix = slab*6 + w; lane owns columns iy in {lane, lane+32, lane+64}.
// Column masks accumulate in registers (no atomics); block writes floats.
// ---------------------------------------------------------------------------
__global__ void __launch_bounds__(192) vox_kernel(float* __restrict__ out)
{
    extern __shared__ float4 smem[];
    float4* sfac = smem;                                  // [NF*8]
    int4*   sbb  = reinterpret_cast<int4*>(smem + NF*8);  // [NF]

    const int b    = blockIdx.x >> 4;
    const int slab = blockIdx.x & (NSLAB - 1);
    const int slot = b * NSLAB + slab;
    const int n    = g_cnt[slot];
    const int* lst = g_list + slot * NF;

    // stage records of this slab's facets: [i*8+0..3]=interval, [4..7]=exact
    for (int i = threadIdx.x; i < n * 8; i += 192) {
        const int f = lst[i >> 3];
        const int w = i & 7;
        sfac[i] = (w < 4) ? g_int[f*4 + w] : g_ex[f*4 + (w - 4)];
    }
    for (int i = threadIdx.x; i < n; i += 192)
        sbb[i] = g_bb[lst[i]];
    __syncthreads();

    const int warp = threadIdx.x >> 5;
    const int lane = threadIdx.x & 31;
    const int ix   = slab * SLABW + warp;
    const float px = (float)(2 * ix + 1 - VOX) / 96.0f;

    unsigned m[3][3] = {{0u,0u,0u},{0u,0u,0u},{0u,0u,0u}};  // [ytile][zword]

    for (int i = 0; i < n; i++) {
        const int4 bb = sbb[i];
        if (ix < bb.x || ix > bb.y) continue;   // warp-uniform

        const float4 q0 = sfac[i*8+0];
        const float4 q1 = sfac[i*8+1];
        const float4 q2 = sfac[i*8+2];
        const float4 q3 = sfac[i*8+3];

        const float h0 = fmaf(q0.x, px, q0.z);
        const float h1 = fmaf(q1.x, px, q1.z);
        const float h2 = fmaf(q2.x, px, q2.z);
        const float h3 = fmaf(q3.x, px, q3.z);

        const int tLo = bb.z >> 5;
        const int tHi = bb.w >> 5;

        #pragma unroll
        for (int t = 0; t < 3; t++) {
            if (t < tLo || t > tHi) continue;
            const int iy = t * 32 + lane;
            if (iy < bb.z || iy > bb.w) continue;
            const float py = (float)(2 * iy + 1 - VOX) / 96.0f;

            const float lo0 = fmaf(q0.y, py, h0);
            const float lo1 = fmaf(q1.y, py, h1);
            const float lo2 = fmaf(q2.y, py, h2);
            const float lo3 = fmaf(q3.y, py, h3);

            const float tlo = fmaxf(fmaxf(lo0, lo1), fmaxf(lo2, lo3));
            const float thi = fminf(fminf(lo0 + q0.w, lo1 + q1.w),
                                    fminf(lo2 + q2.w, lo3 + q3.w));

            if (thi + DELTA < tlo - DELTA || thi < -DELTA || tlo > 95.0f + DELTA)
                continue;

            const int kLo = max(0,  __float2int_ru(tlo - DELTA));
            const int kHi = min(95, __float2int_rd(thi + DELTA));
            if (kLo > kHi) continue;

            const int cLo = max(kLo, __float2int_ru(tlo + DELTA));
            const int cHi = min(kHi, __float2int_rd(thi - DELTA));

            unsigned mw0 = 0u, mw1 = 0u, mw2 = 0u;
            if (cLo <= cHi) {
                #pragma unroll
                for (int w = 0; w < 3; w++) {
                    const int base = 32 * w;
                    const int lo_w = min(max(cLo - base, 0), 32);
                    const int hi_w = min(max(cHi + 1 - base, 0), 32);
                    unsigned mm = 0u;
                    if (lo_w < hi_w)
                        mm = (0xFFFFFFFFu >> (32 - (hi_w - lo_w))) << lo_w;
                    if (w == 0) mw0 = mm; else if (w == 1) mw1 = mm; else mw2 = mm;
                }
            }

            if (kLo < cLo || cHi < kHi) {
                // delta-band voxels: exact re-test (reference-identical form)
                const float4 e0 = sfac[i*8+4];
                const float4 e1 = sfac[i*8+5];
                const float4 e2 = sfac[i*8+6];
                const float4 e3 = sfac[i*8+7];
                const float dx = px - e1.w;
                const float dy = py - e2.w;
                for (int k = kLo; k <= kHi; k++) {
                    if (k >= cLo && k <= cHi) { k = cHi; continue; }
                    const float pz = (float)(2 * k + 1 - VOX) / 96.0f;
                    const float dz = pz - e3.x;
                    const float n0 = fmaf(e0.x, dx, fmaf(e0.y, dy, e0.z * dz));
                    const float n1 = fmaf(e1.x, dx, fmaf(e1.y, dy, e1.z * dz));
                    const float n2 = fmaf(e2.x, dx, fmaf(e2.y, dy, e2.z * dz));
                    const float s  = n0 + n1 + n2;
                    const float lo = fminf(fminf(n0, n1), fminf(n2, s));
                    const float hi = fmaxf(fmaxf(n0, n1), fmaxf(n2, s));
                    if (lo >= 0.0f && hi <= e0.w) {
                        if (k < 32)      mw0 |= 1u << k;
                        else if (k < 64) mw1 |= 1u << (k - 32);
                        else             mw2 |= 1u << (k - 64);
                    }
                }
            }

            m[t][0] |= mw0;  m[t][1] |= mw1;  m[t][2] |= mw2;
        }
    }

    // expand registers -> floats; every column of this slab is written
    #pragma unroll
    for (int t = 0; t < 3; t++) {
        const int iy = t * 32 + lane;
        float4* o4 = reinterpret_cast<float4*>(
            out + (((size_t)(b * VOX + ix) * VOX + iy) * VOX));
        #pragma unroll
        for (int w = 0; w < 3; w++) {
            const unsigned mm = m[t][w];
            #pragma unroll
            for (int j = 0; j < 8; j++) {
                float4 v;
                v.x = (mm >> (j*4 + 0)) & 1u ? 1.0f : 0.0f;
                v.y = (mm >> (j*4 + 1)) & 1u ? 1.0f : 0.0f;
                v.z = (mm >> (j*4 + 2)) & 1u ? 1.0f : 0.0f;
                v.w = (mm >> (j*4 + 3)) & 1u ? 1.0f : 0.0f;
                o4[w*8 + j] = v;
            }
        }
    }
}

extern "C" void kernel_launch(void* const* d_in, const int* in_sizes, int n_in,
                              void* d_out, int out_size)
{
    const float* vertices = (const float*)d_in[0];   // [8, 2048, 3] f32
    const int*   facets   = (const int*)d_in[1];     // [8, 512, 4]  i32
    float* out = (float*)d_out;                      // [8, 96, 96, 96] f32

    const int smem_bytes = NF * 8 * sizeof(float4) + NF * sizeof(int4); // 73728
    static int attr_done = 0;
    cudaFuncSetAttribute(vox_kernel,
                         cudaFuncAttributeMaxDynamicSharedMemorySize, smem_bytes);
    (void)attr_done;

    zero_cnt_kernel<<<1, NB * NSLAB>>>();
    prep_kernel<<<16, 256>>>(vertices, facets);
    vox_kernel<<<NB * NSLAB, 192, smem_bytes>>>(out);
}

// round 8
// speedup vs baseline: 2.7386x; 2.7386x over previous
#include <cuda_runtime.h>
#include <cuda_bf16.h>

#define NB    8
#define NV    2048
#define NF    512
#define VOX   96
#define DELTA 0.03125f

#define STEPF (2.0f / 96.0f)
#define PZ0F  (-95.0f / 96.0f)

// Combined per-facet record, 8 float4 (128B), interleaved:
//  [0..3] interval rows r=0..2,s :  (Ex, Ey, Ec, w)
//         lo_r = Ex*px + Ey*py + Ec ;  hi_r = lo_r + w  (w >= 0)
//  [4..7] exact record (bit-identical R2 form):
//         e0 = B00 B01 B02 |det|   e1 = B10 B11 B12 v3x
//         e2 = B20 B21 B22 v3y     e3 = v3z pad pad pad
__device__ float4 g_rec[NB * NF * 8];
__device__ int4   g_bb [NB * NF];    // voxel bbox (ixLo,ixHi,iyLo,iyHi)

// ---------------------------------------------------------------------------
// Prep: one thread per facet. Records + bbox. No atomics, no lists.
// ---------------------------------------------------------------------------
__global__ void prep_kernel(
    const float* __restrict__ vertices,   // [NB, NV, 3] f32
    const int*   __restrict__ facets)     // [NB, NF, 4] i32
{
    const int id = blockIdx.x * 256 + threadIdx.x;   // < NB*NF
    const int b = id >> 9;

    const float* Vb = vertices + (size_t)b * NV * 3;
    const int* Fp = facets + (size_t)id * 4;
    const int i0 = Fp[0] & (NV - 1);
    const int i1 = Fp[1] & (NV - 1);
    const int i2 = Fp[2] & (NV - 1);
    const int i3 = Fp[3] & (NV - 1);

    const float v0x = Vb[i0*3+0], v0y = Vb[i0*3+1], v0z = Vb[i0*3+2];
    const float v1x = Vb[i1*3+0], v1y = Vb[i1*3+1], v1z = Vb[i1*3+2];
    const float v2x = Vb[i2*3+0], v2y = Vb[i2*3+1], v2z = Vb[i2*3+2];
    const float v3x = Vb[i3*3+0], v3y = Vb[i3*3+1], v3z = Vb[i3*3+2];

    const float a  = v0x - v3x, bb = v1x - v3x, c  = v2x - v3x;
    const float d  = v0y - v3y, e  = v1y - v3y, ff = v2y - v3y;
    const float g  = v0z - v3z, h  = v1z - v3z, ii = v2z - v3z;

    const float A00 = e*ii - ff*h, A01 = c*h  - bb*ii, A02 = bb*ff - c*e;
    const float A10 = ff*g - d*ii, A11 = a*ii - c*g,   A12 = c*d  - a*ff;
    const float A20 = d*h  - e*g,  A21 = bb*g - a*h,   A22 = a*e  - bb*d;

    const float det = a*A00 + bb*A10 + c*A20;
    const float sd  = (det < 0.0f) ? -1.0f : 1.0f;
    float D = det * sd;
    if (det == 0.0f) D = -1.0f;

    const float B[3][3] = { {A00*sd, A01*sd, A02*sd},
                            {A10*sd, A11*sd, A12*sd},
                            {A20*sd, A21*sd, A22*sd} };

    float4* rec = g_rec + (size_t)id * 8;

    // interval rows: rows 0..2 and the s-row (sum)
    float R0[4], R1[4], Kc[4], Bz[4];
    #pragma unroll
    for (int r = 0; r < 3; r++) {
        R0[r] = B[r][0]; R1[r] = B[r][1];
        float bz = B[r][2];
        if (fabsf(bz) < 1e-30f) bz = 1e-30f;
        Bz[r] = bz;
        Kc[r] = bz * (PZ0F - v3z) - B[r][0]*v3x - B[r][1]*v3y;
    }
    R0[3] = R0[0] + R0[1] + R0[2];
    R1[3] = R1[0] + R1[1] + R1[2];
    {
        float bz = Bz[0] + Bz[1] + Bz[2];
        if (fabsf(bz) < 1e-30f) bz = 1e-30f;
        Bz[3] = bz;
        Kc[3] = Kc[0] + Kc[1] + Kc[2];
    }

    #pragma unroll
    for (int r = 0; r < 4; r++) {
        const float G   = Bz[r] * STEPF;
        const float nG  = -1.0f / G;
        const float DoG = D / G;
        rec[r] = make_float4(R0[r] * nG, R1[r] * nG,
                             Kc[r] * nG + fminf(DoG, 0.0f), fabsf(DoG));
    }

    rec[4] = make_float4(B[0][0], B[0][1], B[0][2], D);
    rec[5] = make_float4(B[1][0], B[1][1], B[1][2], v3x);
    rec[6] = make_float4(B[2][0], B[2][1], B[2][2], v3y);
    rec[7] = make_float4(v3z, 0.0f, 0.0f, 0.0f);

    // voxel bbox with safety pad
    const float pad = 1e-5f;
    const float xmn = fminf(fminf(v0x, v1x), fminf(v2x, v3x)) - pad;
    const float xmx = fmaxf(fmaxf(v0x, v1x), fmaxf(v2x, v3x)) + pad;
    const float ymn = fminf(fminf(v0y, v1y), fminf(v2y, v3y)) - pad;
    const float ymx = fmaxf(fmaxf(v0y, v1y), fmaxf(v2y, v3y)) + pad;

    int4 bbv;
    bbv.x = max(0,  (int)ceilf (48.0f * xmn + 47.5f));
    bbv.y = min(95, (int)floorf(48.0f * xmx + 47.5f));
    bbv.z = max(0,  (int)ceilf (48.0f * ymn + 47.5f));
    bbv.w = min(95, (int)floorf(48.0f * ymx + 47.5f));
    if (D < 0.0f) { bbv.x = 1; bbv.y = 0; }   // degenerate: empty
    g_bb[id] = bbv;
}

// ---------------------------------------------------------------------------
// Voxelize: block = (x-plane, batch), 384 threads = 12 warps.
// Warp = (y-tile t = warp>>2, facet-quarter q = warp&3). Lane owns column
// iy = t*32+lane; its 96-bit z-mask accumulates in 3 registers. Block
// compacts the plane's facet list from bboxes, stages records in smem,
// merges warp masks via smem atomicOr, writes floats coalesced.
// ---------------------------------------------------------------------------
__global__ void __launch_bounds__(384) vox_kernel(float* __restrict__ out)
{
    extern __shared__ char smem[];
    float4*   sfac = reinterpret_cast<float4*>(smem);                 // 512*8
    int2*     sbby = reinterpret_cast<int2*>(smem + 65536);           // 512
    int*      slist= reinterpret_cast<int*> (smem + 65536 + 4096);    // 512
    unsigned* sacc = reinterpret_cast<unsigned*>(smem + 65536 + 4096 + 2048); // 96*3
    int*      scnt = reinterpret_cast<int*>(smem + 65536 + 4096 + 2048 + 1152);

    const int tid   = threadIdx.x;
    const int plane = blockIdx.x;
    const int b     = blockIdx.y;

    if (tid == 0) *scnt = 0;
    for (int i = tid; i < VOX * 3; i += 384) sacc[i] = 0u;
    __syncthreads();

    // compact facets overlapping this x-plane
    for (int j = tid; j < NF; j += 384) {
        const int4 bb = g_bb[b * NF + j];
        if (plane >= bb.x && plane <= bb.y) {
            const int pos = atomicAdd(scnt, 1);
            slist[pos] = j;
            sbby[pos] = make_int2(bb.z, bb.w);
        }
    }
    __syncthreads();
    const int n = *scnt;

    // stage records (coalesced: 8 float4 per facet)
    for (int i = tid; i < n * 8; i += 384)
        sfac[i] = g_rec[((size_t)b * NF + slist[i >> 3]) * 8 + (i & 7)];
    __syncthreads();

    const int warp = tid >> 5;
    const int lane = tid & 31;
    const int t = warp >> 2;        // y-tile 0..2
    const int q = warp & 3;         // facet quarter 0..3

    const float px = (float)(2 * plane + 1 - VOX) / 96.0f;
    const int   iy = t * 32 + lane;
    const float py = (float)(2 * iy + 1 - VOX) / 96.0f;

    unsigned m0 = 0u, m1 = 0u, m2 = 0u;

    for (int i = q; i < n; i += 4) {
        const int2 by = sbby[i];
        if ((by.x >> 5) > t || (by.y >> 5) < t) continue;   // warp-uniform
        if (iy < by.x || iy > by.y) continue;               // per-lane

        const float4 q0 = sfac[i*8+0];
        const float4 q1 = sfac[i*8+1];
        const float4 q2 = sfac[i*8+2];
        const float4 q3 = sfac[i*8+3];

        const float lo0 = fmaf(q0.x, px, fmaf(q0.y, py, q0.z));
        const float lo1 = fmaf(q1.x, px, fmaf(q1.y, py, q1.z));
        const float lo2 = fmaf(q2.x, px, fmaf(q2.y, py, q2.z));
        const float lo3 = fmaf(q3.x, px, fmaf(q3.y, py, q3.z));

        const float tlo = fmaxf(fmaxf(lo0, lo1), fmaxf(lo2, lo3));
        const float thi = fminf(fminf(lo0 + q0.w, lo1 + q1.w),
                                fminf(lo2 + q2.w, lo3 + q3.w));

        if (thi + DELTA < tlo - DELTA || thi < -DELTA || tlo > 95.0f + DELTA)
            continue;

        const int kLo = max(0,  __float2int_ru(tlo - DELTA));
        const int kHi = min(95, __float2int_rd(thi + DELTA));
        if (kLo > kHi) continue;

        const int cLo = max(kLo, __float2int_ru(tlo + DELTA));
        const int cHi = min(kHi, __float2int_rd(thi - DELTA));

        unsigned mw0 = 0u, mw1 = 0u, mw2 = 0u;
        if (cLo <= cHi) {
            #pragma unroll
            for (int w = 0; w < 3; w++) {
                const int base = 32 * w;
                const int lo_w = min(max(cLo - base, 0), 32);
                const int hi_w = min(max(cHi + 1 - base, 0), 32);
                unsigned mm = 0u;
                if (lo_w < hi_w)
                    mm = (0xFFFFFFFFu >> (32 - (hi_w - lo_w))) << lo_w;
                if (w == 0) mw0 = mm; else if (w == 1) mw1 = mm; else mw2 = mm;
            }
        }

        if (kLo < cLo || cHi < kHi) {
            // delta-band voxels: exact re-test (reference-identical form)
            const float4 e0 = sfac[i*8+4];
            const float4 e1 = sfac[i*8+5];
            const float4 e2 = sfac[i*8+6];
            const float4 e3 = sfac[i*8+7];
            const float dx = px - e1.w;
            const float dy = py - e2.w;
            for (int k = kLo; k <= kHi; k++) {
                if (k >= cLo && k <= cHi) { k = cHi; continue; }
                const float pz = (float)(2 * k + 1 - VOX) / 96.0f;
                const float dz = pz - e3.x;
                const float n0 = fmaf(e0.x, dx, fmaf(e0.y, dy, e0.z * dz));
                const float n1 = fmaf(e1.x, dx, fmaf(e1.y, dy, e1.z * dz));
                const float n2 = fmaf(e2.x, dx, fmaf(e2.y, dy, e2.z * dz));
                const float s  = n0 + n1 + n2;
                const float lo = fminf(fminf(n0, n1), fminf(n2, s));
                const float hi = fmaxf(fmaxf(n0, n1), fmaxf(n2, s));
                if (lo >= 0.0f && hi <= e0.w) {
                    if (k < 32)      m0 |= 1u << k;
                    else if (k < 64) m1 |= 1u << (k - 32);
                    else             m2 |= 1u << (k - 64);
                }
            }
        }

        m0 |= mw0;  m1 |= mw1;  m2 |= mw2;
    }

    // merge the 4 quarter-warps per column (block-local, cheap)
    if (m0) atomicOr(&sacc[iy * 3 + 0], m0);
    if (m1) atomicOr(&sacc[iy * 3 + 1], m1);
    if (m2) atomicOr(&sacc[iy * 3 + 2], m2);
    __syncthreads();

    // coalesced expand: 96 columns * 24 float4 each
    float4* o4 = reinterpret_cast<float4*>(
        out + ((size_t)(b * VOX + plane) * VOX) * VOX);
    for (int idx = tid; idx < VOX * 24; idx += 384) {
        const int c = idx / 24;
        const int j = idx - c * 24;
        const unsigned word = sacc[c * 3 + (j >> 3)];
        const unsigned nib = (word >> ((j & 7) * 4)) & 0xFu;
        float4 v;
        v.x = (nib & 1u) ? 1.0f : 0.0f;
        v.y = (nib & 2u) ? 1.0f : 0.0f;
        v.z = (nib & 4u) ? 1.0f : 0.0f;
        v.w = (nib & 8u) ? 1.0f : 0.0f;
        o4[c * 24 + j] = v;
    }
}

extern "C" void kernel_launch(void* const* d_in, const int* in_sizes, int n_in,
                              void* d_out, int out_size)
{
    const float* vertices = (const float*)d_in[0];   // [8, 2048, 3] f32
    const int*   facets   = (const int*)d_in[1];     // [8, 512, 4]  i32
    float* out = (float*)d_out;                      // [8, 96, 96, 96] f32

    const int smem_bytes = 65536 + 4096 + 2048 + 1152 + 16;   // 72848
    cudaFuncSetAttribute(vox_kernel,
                         cudaFuncAttributeMaxDynamicSharedMemorySize, smem_bytes);

    prep_kernel<<<16, 256>>>(vertices, facets);
    dim3 grid(VOX, NB);
    vox_kernel<<<grid, 384, smem_bytes>>>(out);
}

// round 11
// speedup vs baseline: 3.1952x; 1.1668x over previous
#include <cuda_runtime.h>
#include <cuda_bf16.h>

#define NB    8
#define NV    2048
#define NF    512
#define VOX   96

#define STEPF (2.0f / 96.0f)
#define PZ0F  (-95.0f / 96.0f)

// Interval record, 4 float4 per facet, rows r=0..2,s:
//  row = (Ex, Ey, Ec, w):  lo_r = Ex*px + Ey*py + Ec ;  hi_r = lo_r + w (w>=0)
__device__ float4 g_int[NB * NF * 4];
// Exact record (bit-identical R2 form), 4 float4 per facet:
//  e0 = B00 B01 B02 |det|   e1 = B10 B11 B12 v3x
//  e2 = B20 B21 B22 v3y     e3 = v3z pad pad pad
__device__ float4 g_ex[NB * NF * 4];
// Packed bbox: {ixLo, ixHi, iyLo|(iyHi<<8), delta_bits}
__device__ int4 g_bb[NB * NF];

// ---------------------------------------------------------------------------
// Prep: one thread per facet.
// ---------------------------------------------------------------------------
__global__ void prep_kernel(
    const float* __restrict__ vertices,   // [NB, NV, 3] f32
    const int*   __restrict__ facets)     // [NB, NF, 4] i32
{
    const int id = blockIdx.x * 256 + threadIdx.x;   // < NB*NF
    const int b = id >> 9;

    const float* Vb = vertices + (size_t)b * NV * 3;
    const int* Fp = facets + (size_t)id * 4;
    const int i0 = Fp[0] & (NV - 1);
    const int i1 = Fp[1] & (NV - 1);
    const int i2 = Fp[2] & (NV - 1);
    const int i3 = Fp[3] & (NV - 1);

    const float v0x = Vb[i0*3+0], v0y = Vb[i0*3+1], v0z = Vb[i0*3+2];
    const float v1x = Vb[i1*3+0], v1y = Vb[i1*3+1], v1z = Vb[i1*3+2];
    const float v2x = Vb[i2*3+0], v2y = Vb[i2*3+1], v2z = Vb[i2*3+2];
    const float v3x = Vb[i3*3+0], v3y = Vb[i3*3+1], v3z = Vb[i3*3+2];

    const float a  = v0x - v3x, bb = v1x - v3x, c  = v2x - v3x;
    const float d  = v0y - v3y, e  = v1y - v3y, ff = v2y - v3y;
    const float g  = v0z - v3z, h  = v1z - v3z, ii = v2z - v3z;

    const float A00 = e*ii - ff*h, A01 = c*h  - bb*ii, A02 = bb*ff - c*e;
    const float A10 = ff*g - d*ii, A11 = a*ii - c*g,   A12 = c*d  - a*ff;
    const float A20 = d*h  - e*g,  A21 = bb*g - a*h,   A22 = a*e  - bb*d;

    const float det = a*A00 + bb*A10 + c*A20;
    const float sd  = (det < 0.0f) ? -1.0f : 1.0f;
    float D = det * sd;
    if (det == 0.0f) D = -1.0f;

    const float B[3][3] = { {A00*sd, A01*sd, A02*sd},
                            {A10*sd, A11*sd, A12*sd},
                            {A20*sd, A21*sd, A22*sd} };

    g_ex[id*4+0] = make_float4(B[0][0], B[0][1], B[0][2], D);
    g_ex[id*4+1] = make_float4(B[1][0], B[1][1], B[1][2], v3x);
    g_ex[id*4+2] = make_float4(B[2][0], B[2][1], B[2][2], v3y);
    g_ex[id*4+3] = make_float4(v3z, 0.0f, 0.0f, 0.0f);

    float R0[4], R1[4], Kc[4], Bz[4];
    #pragma unroll
    for (int r = 0; r < 3; r++) {
        R0[r] = B[r][0]; R1[r] = B[r][1];
        float bz = B[r][2];
        if (fabsf(bz) < 1e-30f) bz = 1e-30f;
        Bz[r] = bz;
        Kc[r] = bz * (PZ0F - v3z) - B[r][0]*v3x - B[r][1]*v3y;
    }
    R0[3] = R0[0] + R0[1] + R0[2];
    R1[3] = R1[0] + R1[1] + R1[2];
    {
        float bz = Bz[0] + Bz[1] + Bz[2];
        if (fabsf(bz) < 1e-30f) bz = 1e-30f;
        Bz[3] = bz;
        Kc[3] = Kc[0] + Kc[1] + Kc[2];
    }

    float M = 0.0f;
    #pragma unroll
    for (int r = 0; r < 4; r++) {
        const float G   = Bz[r] * STEPF;
        const float nG  = -1.0f / G;
        const float DoG = D / G;
        const float Ex  = R0[r] * nG;
        const float Ey  = R1[r] * nG;
        const float Ec  = Kc[r] * nG + fminf(DoG, 0.0f);
        const float w   = fabsf(DoG);
        g_int[id*4+r] = make_float4(Ex, Ey, Ec, w);
        M = fmaxf(M, fabsf(Ex) + fabsf(Ey) + fabsf(Ec) + w);
    }
    const float delta = fmaf(M, 4e-6f, 2e-6f);   // conservative endpoint bound

    // voxel bbox with safety pad
    const float pad = 1e-5f;
    const float xmn = fminf(fminf(v0x, v1x), fminf(v2x, v3x)) - pad;
    const float xmx = fmaxf(fmaxf(v0x, v1x), fmaxf(v2x, v3x)) + pad;
    const float ymn = fminf(fminf(v0y, v1y), fminf(v2y, v3y)) - pad;
    const float ymx = fmaxf(fmaxf(v0y, v1y), fmaxf(v2y, v3y)) + pad;

    int4 bbv;
    bbv.x = max(0,  (int)ceilf (48.0f * xmn + 47.5f));
    bbv.y = min(95, (int)floorf(48.0f * xmx + 47.5f));
    const int iyLo = max(0,  (int)ceilf (48.0f * ymn + 47.5f));
    const int iyHi = min(95, (int)floorf(48.0f * ymx + 47.5f));
    bbv.z = iyLo | (iyHi << 8);
    bbv.w = __float_as_int(delta);
    if (D < 0.0f || iyLo > iyHi) { bbv.x = 1; bbv.y = 0; }   // empty
    g_bb[id] = bbv;
}

// ---------------------------------------------------------------------------
// Voxelize: block = (x-plane, batch), 384 threads = 12 warps.
// Warp = (y-tile t = warp>>2, facet-quarter q = warp&3); lane owns column
// iy = t*32+lane, mask in 3 registers. Fused compaction+staging builds
// per-tile facet lists and px-folded interval coeffs in smem. Exact band
// re-test is rare (tight per-facet delta) and reads g_ex via L2.
// ---------------------------------------------------------------------------
__global__ void __launch_bounds__(384) vox_kernel(float* __restrict__ out)
{
    __shared__ float4   sfac[NF * 3];     // 24576 B  (Ey,Ec',w per row, packed)
    __shared__ int4     sbbe[NF];         //  8192 B  {iyLo, iyHi, delta_bits, fid}
    __shared__ int      tlist[3][NF];     //  6144 B
    __shared__ unsigned sacc[VOX * 3];    //  1152 B
    __shared__ int      tcnt[3];
    __shared__ int      pcnt;

    const int tid   = threadIdx.x;
    const int plane = blockIdx.x;
    const int b     = blockIdx.y;

    if (tid < 3) tcnt[tid] = 0;
    if (tid == 3) pcnt = 0;
    for (int i = tid; i < VOX * 3; i += 384) sacc[i] = 0u;
    __syncthreads();

    const float px = (float)(2 * plane + 1 - VOX) / 96.0f;

    // fused compaction + staging
    for (int j = tid; j < NF; j += 384) {
        const int4 bb = g_bb[b * NF + j];
        if (plane < bb.x || plane > bb.y) continue;
        const int pos = atomicAdd(&pcnt, 1);
        const int iyLo = bb.z & 0xFF, iyHi = (bb.z >> 8) & 0xFF;
        sbbe[pos] = make_int4(iyLo, iyHi, bb.w, j);
        for (int t = iyLo >> 5; t <= iyHi >> 5; t++) {
            const int tp = atomicAdd(&tcnt[t], 1);
            tlist[t][tp] = pos;
        }
        const float4* gi = g_int + ((size_t)b * NF + j) * 4;
        const float4 r0 = gi[0], r1 = gi[1], r2 = gi[2], r3 = gi[3];
        const float Ec0 = fmaf(r0.x, px, r0.z);
        const float Ec1 = fmaf(r1.x, px, r1.z);
        const float Ec2 = fmaf(r2.x, px, r2.z);
        const float Ec3 = fmaf(r3.x, px, r3.z);
        sfac[pos*3+0] = make_float4(r0.y, Ec0, r0.w, r1.y);
        sfac[pos*3+1] = make_float4(Ec1, r1.w, r2.y, Ec2);
        sfac[pos*3+2] = make_float4(r2.w, r3.y, Ec3, r3.w);
    }
    __syncthreads();

    const int warp = tid >> 5;
    const int lane = tid & 31;
    const int t = warp >> 2;        // y-tile 0..2
    const int q = warp & 3;         // facet quarter 0..3

    const int   iy = t * 32 + lane;
    const float py = (float)(2 * iy + 1 - VOX) / 96.0f;

    unsigned m0 = 0u, m1 = 0u, m2 = 0u;
    const int myn = tcnt[t];

    for (int ii = q; ii < myn; ii += 4) {
        const int pos = tlist[t][ii];
        const int4 be = sbbe[pos];
        if (iy < be.x || iy > be.y) continue;

        const float4 a0 = sfac[pos*3+0];
        const float4 a1 = sfac[pos*3+1];
        const float4 a2 = sfac[pos*3+2];

        const float lo0 = fmaf(a0.x, py, a0.y);
        const float lo1 = fmaf(a0.w, py, a1.x);
        const float lo2 = fmaf(a1.z, py, a1.w);
        const float lo3 = fmaf(a2.y, py, a2.z);

        const float tlo = fmaxf(fmaxf(lo0, lo1), fmaxf(lo2, lo3));
        const float thi = fminf(fminf(lo0 + a0.z, lo1 + a1.y),
                                fminf(lo2 + a2.x, lo3 + a2.w));

        const float df = __int_as_float(be.z);
        const bool allex = !(df <= 0.4f);    // pathological (or NaN) facet

        int kLo, kHi, cLo, cHi;
        if (allex) {
            kLo = 0; kHi = 95; cLo = 96; cHi = -1;
        } else {
            kLo = max(0,  __float2int_ru(tlo - df));
            kHi = min(95, __float2int_rd(thi + df));
            if (kLo > kHi) continue;
            cLo = kLo + (((float)kLo < tlo + df) ? 1 : 0);
            cHi = kHi - (((float)kHi > thi - df) ? 1 : 0);
        }

        if (cLo <= cHi) {
            #pragma unroll
            for (int w = 0; w < 3; w++) {
                const int base = 32 * w;
                const int lo_w = min(max(cLo - base, 0), 32);
                const int hi_w = min(max(cHi + 1 - base, 0), 32);
                unsigned mm = 0u;
                if (lo_w < hi_w)
                    mm = (0xFFFFFFFFu >> (32 - (hi_w - lo_w))) << lo_w;
                if (w == 0) m0 |= mm; else if (w == 1) m1 |= mm; else m2 |= mm;
            }
        }

        if (kLo < cLo || cHi < kHi) {
            // rare band: exact re-test (reference-identical form), L2-resident
            const float4* ep = g_ex + ((size_t)b * NF + be.w) * 4;
            const float4 e0 = __ldg(ep + 0);
            const float4 e1 = __ldg(ep + 1);
            const float4 e2 = __ldg(ep + 2);
            const float4 e3 = __ldg(ep + 3);
            const float dx = px - e1.w;
            const float dy = py - e2.w;
            for (int k = kLo; k <= kHi; k++) {
                if (k >= cLo && k <= cHi) { k = cHi; continue; }
                const float pz = (float)(2 * k + 1 - VOX) / 96.0f;
                const float dz = pz - e3.x;
                const float n0 = fmaf(e0.x, dx, fmaf(e0.y, dy, e0.z * dz));
                const float n1 = fmaf(e1.x, dx, fmaf(e1.y, dy, e1.z * dz));
                const float n2 = fmaf(e2.x, dx, fmaf(e2.y, dy, e2.z * dz));
                const float s  = n0 + n1 + n2;
                const float lo = fminf(fminf(n0, n1), fminf(n2, s));
                const float hi = fmaxf(fmaxf(n0, n1), fmaxf(n2, s));
                if (lo >= 0.0f && hi <= e0.w) {
                    if (k < 32)      m0 |= 1u << k;
                    else if (k < 64) m1 |= 1u << (k - 32);
                    else             m2 |= 1u << (k - 64);
                }
            }
        }
    }

    // merge the 4 quarter-warps per column (block-local)
    if (m0) atomicOr(&sacc[iy * 3 + 0], m0);
    if (m1) atomicOr(&sacc[iy * 3 + 1], m1);
    if (m2) atomicOr(&sacc[iy * 3 + 2], m2);
    __syncthreads();

    // coalesced expand: 96 columns * 24 float4 each
    float4* o4 = reinterpret_cast<float4*>(
        out + ((size_t)(b * VOX + plane) * VOX) * VOX);
    for (int idx = tid; idx < VOX * 24; idx += 384) {
        const int c = idx / 24;
        const int j = idx - c * 24;
        const unsigned word = sacc[c * 3 + (j >> 3)];
        const unsigned nib = (word >> ((j & 7) * 4)) & 0xFu;
        float4 v;
        v.x = (nib & 1u) ? 1.0f : 0.0f;
        v.y = (nib & 2u) ? 1.0f : 0.0f;
        v.z = (nib & 4u) ? 1.0f : 0.0f;
        v.w = (nib & 8u) ? 1.0f : 0.0f;
        o4[c * 24 + j] = v;
    }
}

extern "C" void kernel_launch(void* const* d_in, const int* in_sizes, int n_in,
                              void* d_out, int out_size)
{
    const float* vertices = (const float*)d_in[0];   // [8, 2048, 3] f32
    const int*   facets   = (const int*)d_in[1];     // [8, 512, 4]  i32
    float* out = (float*)d_out;                      // [8, 96, 96, 96] f32

    prep_kernel<<<16, 256>>>(vertices, facets);
    dim3 grid(VOX, NB);
    vox_kernel<<<grid, 384>>>(out);
}

// round 13
// speedup vs baseline: 3.4148x; 1.0687x over previous
#include <cuda_runtime.h>
#include <cuda_bf16.h>

#define NB    8
#define NV    2048
#define NF    512
#define VOX   96

#define STEPF (2.0f / 96.0f)
#define PZ0F  (-95.0f / 96.0f)

// Interval record, 4 float4 per facet, rows r=0..2,s:
//  row = (Ex, Ey, Ec, w):  lo_r = Ex*px + Ey*py + Ec ;  hi_r = lo_r + w (w>=0)
__device__ float4 g_int[NB * NF * 4];
// Exact record (bit-identical R2 form), 4 float4 per facet:
//  e0 = B00 B01 B02 |det|   e1 = B10 B11 B12 v3x
//  e2 = B20 B21 B22 v3y     e3 = v3z pad pad pad
__device__ float4 g_ex[NB * NF * 4];
// Packed bbox: {ixLo, ixHi, iyLo|(iyHi<<8), delta_bits}
__device__ int4 g_bb[NB * NF];

// ---------------------------------------------------------------------------
// Prep: one thread per facet.
// ---------------------------------------------------------------------------
__global__ void prep_kernel(
    const float* __restrict__ vertices,   // [NB, NV, 3] f32
    const int*   __restrict__ facets)     // [NB, NF, 4] i32
{
    const int id = blockIdx.x * 256 + threadIdx.x;   // < NB*NF
    const int b = id >> 9;

    const float* Vb = vertices + (size_t)b * NV * 3;
    const int* Fp = facets + (size_t)id * 4;
    const int i0 = Fp[0] & (NV - 1);
    const int i1 = Fp[1] & (NV - 1);
    const int i2 = Fp[2] & (NV - 1);
    const int i3 = Fp[3] & (NV - 1);

    const float v0x = Vb[i0*3+0], v0y = Vb[i0*3+1], v0z = Vb[i0*3+2];
    const float v1x = Vb[i1*3+0], v1y = Vb[i1*3+1], v1z = Vb[i1*3+2];
    const float v2x = Vb[i2*3+0], v2y = Vb[i2*3+1], v2z = Vb[i2*3+2];
    const float v3x = Vb[i3*3+0], v3y = Vb[i3*3+1], v3z = Vb[i3*3+2];

    const float a  = v0x - v3x, bb = v1x - v3x, c  = v2x - v3x;
    const float d  = v0y - v3y, e  = v1y - v3y, ff = v2y - v3y;
    const float g  = v0z - v3z, h  = v1z - v3z, ii = v2z - v3z;

    const float A00 = e*ii - ff*h, A01 = c*h  - bb*ii, A02 = bb*ff - c*e;
    const float A10 = ff*g - d*ii, A11 = a*ii - c*g,   A12 = c*d  - a*ff;
    const float A20 = d*h  - e*g,  A21 = bb*g - a*h,   A22 = a*e  - bb*d;

    const float det = a*A00 + bb*A10 + c*A20;
    const float sd  = (det < 0.0f) ? -1.0f : 1.0f;
    float D = det * sd;
    if (det == 0.0f) D = -1.0f;

    const float B[3][3] = { {A00*sd, A01*sd, A02*sd},
                            {A10*sd, A11*sd, A12*sd},
                            {A20*sd, A21*sd, A22*sd} };

    g_ex[id*4+0] = make_float4(B[0][0], B[0][1], B[0][2], D);
    g_ex[id*4+1] = make_float4(B[1][0], B[1][1], B[1][2], v3x);
    g_ex[id*4+2] = make_float4(B[2][0], B[2][1], B[2][2], v3y);
    g_ex[id*4+3] = make_float4(v3z, 0.0f, 0.0f, 0.0f);

    float R0[4], R1[4], Kc[4], Bz[4];
    #pragma unroll
    for (int r = 0; r < 3; r++) {
        R0[r] = B[r][0]; R1[r] = B[r][1];
        float bz = B[r][2];
        if (fabsf(bz) < 1e-30f) bz = 1e-30f;
        Bz[r] = bz;
        Kc[r] = bz * (PZ0F - v3z) - B[r][0]*v3x - B[r][1]*v3y;
    }
    R0[3] = R0[0] + R0[1] + R0[2];
    R1[3] = R1[0] + R1[1] + R1[2];
    {
        float bz = Bz[0] + Bz[1] + Bz[2];
        if (fabsf(bz) < 1e-30f) bz = 1e-30f;
        Bz[3] = bz;
        Kc[3] = Kc[0] + Kc[1] + Kc[2];
    }

    float M = 0.0f;
    #pragma unroll
    for (int r = 0; r < 4; r++) {
        const float G   = Bz[r] * STEPF;
        const float nG  = -1.0f / G;
        const float DoG = D / G;
        const float Ex  = R0[r] * nG;
        const float Ey  = R1[r] * nG;
        const float Ec  = Kc[r] * nG + fminf(DoG, 0.0f);
        const float w   = fabsf(DoG);
        g_int[id*4+r] = make_float4(Ex, Ey, Ec, w);
        M = fmaxf(M, fabsf(Ex) + fabsf(Ey) + fabsf(Ec) + w);
    }
    const float delta = fmaf(M, 4e-6f, 2e-6f);   // conservative endpoint bound

    // voxel bbox with safety pad
    const float pad = 1e-5f;
    const float xmn = fminf(fminf(v0x, v1x), fminf(v2x, v3x)) - pad;
    const float xmx = fmaxf(fmaxf(v0x, v1x), fmaxf(v2x, v3x)) + pad;
    const float ymn = fminf(fminf(v0y, v1y), fminf(v2y, v3y)) - pad;
    const float ymx = fmaxf(fmaxf(v0y, v1y), fmaxf(v2y, v3y)) + pad;

    int4 bbv;
    bbv.x = max(0,  (int)ceilf (48.0f * xmn + 47.5f));
    bbv.y = min(95, (int)floorf(48.0f * xmx + 47.5f));
    const int iyLo = max(0,  (int)ceilf (48.0f * ymn + 47.5f));
    const int iyHi = min(95, (int)floorf(48.0f * ymx + 47.5f));
    bbv.z = iyLo | (iyHi << 8);
    bbv.w = __float_as_int(delta);
    if (D < 0.0f || iyLo > iyHi) { bbv.x = 1; bbv.y = 0; }   // empty
    g_bb[id] = bbv;
}

// ---------------------------------------------------------------------------
// Voxelize: block = (x-plane, batch), 384 threads = 12 warps.
// Warp = (y-tile t = warp>>2, facet-quarter q = warp&3); lane owns column
// iy = t*32+lane, mask in 3 registers. Range masks come from a smem
// prefix-mask LUT (GE & LT) instead of shift arithmetic.
// ---------------------------------------------------------------------------
#define LUTP 104   // padded stride per word row

__global__ void __launch_bounds__(384, 3) vox_kernel(float* __restrict__ out)
{
    __shared__ float4   sfac[NF * 3];     // 24576 B (Ey,Ec',w rows packed)
    __shared__ int2     sbbe[NF];         //  4096 B {iyLo|iyHi<<8|fid<<16, delta}
    __shared__ int      tlist[3][NF];     //  6144 B
    __shared__ unsigned sGE[3 * LUTP];    //  1248 B: word w of bits >= k
    __shared__ unsigned sLT[3 * LUTP];    //  1248 B: word w of bits <  k
    __shared__ unsigned sacc[VOX * 3];    //  1152 B
    __shared__ int      tcnt[3];
    __shared__ int      pcnt;

    const int tid   = threadIdx.x;
    const int plane = blockIdx.x;
    const int b     = blockIdx.y;

    if (tid < 3) tcnt[tid] = 0;
    if (tid == 3) pcnt = 0;
    for (int i = tid; i < VOX * 3; i += 384) sacc[i] = 0u;
    // build prefix-mask LUT: 3 words x 97 entries
    for (int i = tid; i < 3 * 97; i += 384) {
        const int w = i / 97;
        const int k = i - w * 97;
        const int s = k - 32 * w;          // relative bit position
        unsigned ge, lt;
        if (s <= 0)       { ge = 0xFFFFFFFFu; lt = 0u; }
        else if (s >= 32) { ge = 0u;          lt = 0xFFFFFFFFu; }
        else              { ge = 0xFFFFFFFFu << s; lt = 0xFFFFFFFFu >> (32 - s); }
        sGE[w * LUTP + k] = ge;
        sLT[w * LUTP + k] = lt;
    }
    __syncthreads();

    const float px = (float)(2 * plane + 1 - VOX) / 96.0f;

    // fused compaction + staging
    for (int j = tid; j < NF; j += 384) {
        const int4 bb = g_bb[b * NF + j];
        if (plane < bb.x || plane > bb.y) continue;
        const int pos = atomicAdd(&pcnt, 1);
        const int iyLo = bb.z & 0xFF, iyHi = (bb.z >> 8) & 0xFF;
        sbbe[pos] = make_int2((bb.z & 0xFFFF) | (j << 16), bb.w);
        for (int t = iyLo >> 5; t <= iyHi >> 5; t++) {
            const int tp = atomicAdd(&tcnt[t], 1);
            tlist[t][tp] = pos;
        }
        const float4* gi = g_int + ((size_t)b * NF + j) * 4;
        const float4 r0 = gi[0], r1 = gi[1], r2 = gi[2], r3 = gi[3];
        const float Ec0 = fmaf(r0.x, px, r0.z);
        const float Ec1 = fmaf(r1.x, px, r1.z);
        const float Ec2 = fmaf(r2.x, px, r2.z);
        const float Ec3 = fmaf(r3.x, px, r3.z);
        sfac[pos*3+0] = make_float4(r0.y, Ec0, r0.w, r1.y);
        sfac[pos*3+1] = make_float4(Ec1, r1.w, r2.y, Ec2);
        sfac[pos*3+2] = make_float4(r2.w, r3.y, Ec3, r3.w);
    }
    __syncthreads();

    const int warp = tid >> 5;
    const int lane = tid & 31;
    const int t = warp >> 2;        // y-tile 0..2
    const int q = warp & 3;         // facet quarter 0..3

    const int   iy = t * 32 + lane;
    const float py = (float)(2 * iy + 1 - VOX) / 96.0f;

    unsigned m0 = 0u, m1 = 0u, m2 = 0u;
    const int myn = tcnt[t];

    for (int ii = q; ii < myn; ii += 4) {
        const int pos = tlist[t][ii];
        const int2 be = sbbe[pos];
        const int iyLo = be.x & 0xFF;
        const int iyHi = (be.x >> 8) & 0xFF;
        if (iy < iyLo || iy > iyHi) continue;

        const float4 a0 = sfac[pos*3+0];
        const float4 a1 = sfac[pos*3+1];
        const float4 a2 = sfac[pos*3+2];

        const float lo0 = fmaf(a0.x, py, a0.y);
        const float lo1 = fmaf(a0.w, py, a1.x);
        const float lo2 = fmaf(a1.z, py, a1.w);
        const float lo3 = fmaf(a2.y, py, a2.z);

        const float tlo = fmaxf(fmaxf(lo0, lo1), fmaxf(lo2, lo3));
        const float thi = fminf(fminf(lo0 + a0.z, lo1 + a1.y),
                                fminf(lo2 + a2.x, lo3 + a2.w));

        const float df = __int_as_float(be.y);
        const bool allex = !(df <= 0.4f);    // pathological (or NaN) facet

        int kLo, kHi, cLo, cHi;
        if (allex) {
            kLo = 0; kHi = 95; cLo = 96; cHi = -1;
        } else {
            kLo = max(0,  __float2int_ru(tlo - df));
            kHi = min(95, __float2int_rd(thi + df));
            if (kLo > kHi) continue;
            cLo = kLo + (((float)kLo < tlo + df) ? 1 : 0);
            cHi = kHi - (((float)kHi > thi - df) ? 1 : 0);
        }

        // clear-region mask via prefix LUT (empty case falls out as 0)
        {
            const int aI = cLo;          // 0..96
            const int bI = cHi + 1;      // 0..96
            m0 |= sGE[aI]            & sLT[bI];
            m1 |= sGE[LUTP + aI]     & sLT[LUTP + bI];
            m2 |= sGE[2 * LUTP + aI] & sLT[2 * LUTP + bI];
        }

        if (kLo < cLo || cHi < kHi) {
            // rare band: exact re-test (reference-identical form), L2-resident
            const int fid = (be.x >> 16) & 0xFFFF;
            const float4* ep = g_ex + ((size_t)b * NF + fid) * 4;
            const float4 e0 = __ldg(ep + 0);
            const float4 e1 = __ldg(ep + 1);
            const float4 e2 = __ldg(ep + 2);
            const float4 e3 = __ldg(ep + 3);
            const float dx = px - e1.w;
            const float dy = py - e2.w;
            for (int k = kLo; k <= kHi; k++) {
                if (k >= cLo && k <= cHi) { k = cHi; continue; }
                const float pz = (float)(2 * k + 1 - VOX) / 96.0f;
                const float dz = pz - e3.x;
                const float n0 = fmaf(e0.x, dx, fmaf(e0.y, dy, e0.z * dz));
                const float n1 = fmaf(e1.x, dx, fmaf(e1.y, dy, e1.z * dz));
                const float n2 = fmaf(e2.x, dx, fmaf(e2.y, dy, e2.z * dz));
                const float s  = n0 + n1 + n2;
                const float lo = fminf(fminf(n0, n1), fminf(n2, s));
                const float hi = fmaxf(fmaxf(n0, n1), fmaxf(n2, s));
                if (lo >= 0.0f && hi <= e0.w) {
                    if (k < 32)      m0 |= 1u << k;
                    else if (k < 64) m1 |= 1u << (k - 32);
                    else             m2 |= 1u << (k - 64);
                }
            }
        }
    }

    // merge the 4 quarter-warps per column (block-local)
    if (m0) atomicOr(&sacc[iy * 3 + 0], m0);
    if (m1) atomicOr(&sacc[iy * 3 + 1], m1);
    if (m2) atomicOr(&sacc[iy * 3 + 2], m2);
    __syncthreads();

    // coalesced expand: 96 columns * 24 float4 each
    float4* o4 = reinterpret_cast<float4*>(
        out + ((size_t)(b * VOX + plane) * VOX) * VOX);
    for (int idx = tid; idx < VOX * 24; idx += 384) {
        const int c = idx / 24;
        const int j = idx - c * 24;
        const unsigned word = sacc[c * 3 + (j >> 3)];
        const unsigned nib = (word >> ((j & 7) * 4)) & 0xFu;
        float4 v;
        v.x = (nib & 1u) ? 1.0f : 0.0f;
        v.y = (nib & 2u) ? 1.0f : 0.0f;
        v.z = (nib & 4u) ? 1.0f : 0.0f;
        v.w = (nib & 8u) ? 1.0f : 0.0f;
        o4[c * 24 + j] = v;
    }
}

extern "C" void kernel_launch(void* const* d_in, const int* in_sizes, int n_in,
                              void* d_out, int out_size)
{
    const float* vertices = (const float*)d_in[0];   // [8, 2048, 3] f32
    const int*   facets   = (const int*)d_in[1];     // [8, 512, 4]  i32
    float* out = (float*)d_out;                      // [8, 96, 96, 96] f32

    prep_kernel<<<16, 256>>>(vertices, facets);
    dim3 grid(VOX, NB);
    vox_kernel<<<grid, 384>>>(out);
}